// round 16
// baseline (speedup 1.0000x reference)
#include <cuda_runtime.h>
#include <cuda_fp16.h>
#include <math.h>

#define NSC 7
#define NB 8
#define ADIM 512
#define MAPSZ (NB * ADIM * ADIM)       // 2,097,152 cells per scale
#define PTS (NSC * MAPSZ)              // 14,680,064 points per coord set
#define TTY 258                        // tile-row stride (even for uint4)
#define TTX 257                        // tile rows
#define MAPH (TTX * TTY)               // 66306 tiles (8B each) per (map, replica)

// Scratch: 4 shift-replicas per scale; each 2x2 logical tile = 4 x f16 = uint2.
// ~119 MB. INVARIANT: all-zero at entry to every kernel_launch call
// (__device__ globals zero-init at load; k_stats/k_sweep re-zero after use).
__device__ __align__(16) uint2 g_rep[NSC][4][NB * MAPH];
__device__ unsigned int g_mask[MAPSZ / 32];   // 1 bit/cell; fully rewritten each call
__device__ float        g_sumlog[NSC];
__device__ unsigned int g_max[NSC];     // float bits (values >= 0)
__device__ unsigned int g_nzero[NSC];
__device__ unsigned int g_npos;

// ---------------------------------------------------------------------------
// K1: bilinear scatter, ALL scales — ONE red.global.add.noftz.v2.f16x2 per
// point (at the LTS vector-atomic floor; width/residency effects falsified).
// Replica (sx,sy) stores logical (x,y) at (x+sx, y+sy). Tile halves [0..3] =
// (dx,dy) = (0,0),(0,1),(1,0),(1,1). First 65536 threads also build the
// target bitmask (uses scatter's issue slack).
// ---------------------------------------------------------------------------
__device__ __forceinline__ void scat1(int s, int b, float r, float c) {
    float xf = fminf(fmaxf(floorf(r), 0.f), 511.f);
    float yf = fminf(fmaxf(floorf(c), 0.f), 511.f);
    float xw = r - xf;
    float yw = c - yf;
    int ix = (int)xf, iy = (int)yf;
    int sx = ix & 1, sy = iy & 1;
    uint2* a = &g_rep[s][sx * 2 + sy][b * MAPH + ((ix + sx) >> 1) * TTY + ((iy + sy) >> 1)];
    float wx0 = 1.f - xw, wy0 = 1.f - yw;
    __half2 lo = __floats2half2_rn(wx0 * wy0, wx0 * yw);   // (0,0),(0,1)
    __half2 hi = __floats2half2_rn(xw * wy0,  xw * yw);    // (1,0),(1,1)
    unsigned ulo = *reinterpret_cast<unsigned*>(&lo);
    unsigned uhi = *reinterpret_cast<unsigned*>(&hi);
    asm volatile("red.global.add.noftz.v2.f16x2 [%0], {%1, %2};"
                 :: "l"(a), "r"(ulo), "r"(uhi)
                 : "memory");
}

__global__ void __launch_bounds__(256) k_scatter(
        const float4* __restrict__ r3, const float4* __restrict__ c3,
        const float4* __restrict__ r4, const float4* __restrict__ c4,
        const float4* __restrict__ target) {
    int i = blockIdx.x * blockDim.x + threadIdx.x;   // [0, PTS/4)

    // Fused mask build: bit c of word (b*512+r)*16 + c/32 = (target==1).
    if (i < MAPSZ / 32) {
        const float4* tp = target + i * 8;           // 32 cells
        unsigned m = 0;
        #pragma unroll
        for (int j = 0; j < 8; j++) {
            float4 t = tp[j];
            m |= (t.x == 1.0f ? 1u : 0u) << (4 * j);
            m |= (t.y == 1.0f ? 2u : 0u) << (4 * j);
            m |= (t.z == 1.0f ? 4u : 0u) << (4 * j);
            m |= (t.w == 1.0f ? 8u : 0u) << (4 * j);
        }
        g_mask[i] = m;
    }

    if (i >= PTS / 4) return;
    int s = i >> 19;                                 // scale (MAPSZ/4 = 2^19)
    int b = (i >> 16) & 7;                           // batch within scale

    float4 rA = r3[i], cA = c3[i];
    float4 rB = r4[i], cB = c4[i];
    scat1(s, b, rA.x, cA.x); scat1(s, b, rA.y, cA.y);
    scat1(s, b, rA.z, cA.z); scat1(s, b, rA.w, cA.w);
    scat1(s, b, rB.x, cB.x); scat1(s, b, rB.y, cB.y);
    scat1(s, b, rB.z, cB.z); scat1(s, b, rB.w, cB.w);
}

// ---------------------------------------------------------------------------
// K2: fused combine + max + masked log-stats + INTERIOR restore-to-zero.
// CTA = 16x32 = 512 threads over (bx block-of-16, byp block-of-32); one
// home-pair per thread. Cross-CTA reads only touch ty==0 rows (rows % 16)
// and tx==0 cols of neighbor blocks — never zeroed here (k_sweep gets them).
// Order: compute -> CTA reduce -> accumulator atomics -> PDL TRIGGER ->
// interior zeroing. Sweep (disjoint tiles, reads only accumulators) can
// therefore overlap the zero-store tail.
// BCE algebra: sum_{mask} min(lm - log(dm), 100)
//   = (npos - nzero)*lm - sum_{mask,dm>0} log(dm) + 100*nzero
// ---------------------------------------------------------------------------
__device__ __forceinline__ float lohalf(unsigned u) { return __half2float(__ushort_as_half((unsigned short)(u & 0xFFFF))); }
__device__ __forceinline__ float hihalf(unsigned u) { return __half2float(__ushort_as_half((unsigned short)(u >> 16))); }

__device__ __forceinline__ void stat_cell(float d, unsigned bit, float& sl,
                                          unsigned& nz) {
    if (bit) {
        if (d == 0.f) nz++;
        else sl += __logf(d);
    }
}

__global__ void __launch_bounds__(512) k_stats() {
    // blockIdx.x in [0, 3584): s(7) | b(8) | bxblk(16) | bypblk(4)
    const int s      = blockIdx.x >> 9;
    const int rem    = blockIdx.x & 511;
    const int b      = rem >> 6;
    const int bxblk  = (rem >> 2) & 15;
    const int bypblk = rem & 3;
    const int tx = threadIdx.x & 31;     // byp within block
    const int ty = threadIdx.x >> 5;     // bx within block (0..15)
    const int bx  = bxblk * 16 + ty;
    const int byp = bypblk * 32 + tx;
    const int by  = byp * 2;
    const int t00 = b * MAPH + bx * TTY + by;    // 16B aligned (TTY, by even)

    cudaGridDependencySynchronize();     // wait for scatter (PDL)

    uint2* __restrict__ w00 = g_rep[s][0];
    uint2* __restrict__ w01 = g_rep[s][1];
    uint2* __restrict__ w10 = g_rep[s][2];
    uint2* __restrict__ w11 = g_rep[s][3];

    float mx, sl = 0.f;
    unsigned nz = 0, np = 0;
    {
        uint4 A  = *(const uint4*)(w00 + t00);
        uint4 B0 = *(const uint4*)(w01 + t00);
        uint2 B2 = w01[t00 + 2];
        uint4 C0 = *(const uint4*)(w10 + t00);
        uint4 C1 = *(const uint4*)(w10 + t00 + TTY);
        uint4 D0 = *(const uint4*)(w11 + t00);
        uint2 D2 = w11[t00 + 2];
        uint4 D1 = *(const uint4*)(w11 + t00 + TTY);
        uint2 D3 = w11[t00 + TTY + 2];

        // home tile 0: logical block (bx, by); home tile 1: (bx, by+1)
        float a00 = lohalf(A.x) + hihalf(B0.x) + lohalf(C0.y) + hihalf(D0.y);
        float a01 = hihalf(A.x) + lohalf(B0.z) + hihalf(C0.y) + lohalf(D0.w);
        float a10 = lohalf(A.y) + hihalf(B0.y) + lohalf(C1.x) + hihalf(D1.x);
        float a11 = hihalf(A.y) + lohalf(B0.w) + hihalf(C1.x) + lohalf(D1.z);
        float e00 = lohalf(A.z) + hihalf(B0.z) + lohalf(C0.w) + hihalf(D0.w);
        float e01 = hihalf(A.z) + lohalf(B2.x) + hihalf(C0.w) + lohalf(D2.y);
        float e10 = lohalf(A.w) + hihalf(B0.w) + lohalf(C1.z) + hihalf(D1.z);
        float e11 = hihalf(A.w) + lohalf(B2.y) + hihalf(C1.z) + lohalf(D3.x);

        mx = fmaxf(fmaxf(fmaxf(a00, a01), fmaxf(a10, a11)),
                   fmaxf(fmaxf(e00, e01), fmaxf(e10, e11)));

        // mask: rows 2bx, 2bx+1; logical col base C = 2*by = 4*byp
        const unsigned* mrow = g_mask + ((b * ADIM + 2 * bx) * 16) + (byp >> 3);
        unsigned mw0 = mrow[0];        // row 2bx
        unsigned mw1 = mrow[16];       // row 2bx+1
        int sh = 4 * (byp & 7);
        unsigned m0 = (mw0 >> sh) & 0xFu;   // cols C..C+3 -> a00,a01,e00,e01
        unsigned m1 = (mw1 >> sh) & 0xFu;   // -> a10,a11,e10,e11
        np = __popc(m0) + __popc(m1);

        stat_cell(a00, m0 & 1u, sl, nz);
        stat_cell(a01, m0 & 2u, sl, nz);
        stat_cell(e00, m0 & 4u, sl, nz);
        stat_cell(e01, m0 & 8u, sl, nz);
        stat_cell(a10, m1 & 1u, sl, nz);
        stat_cell(a11, m1 & 2u, sl, nz);
        stat_cell(e10, m1 & 4u, sl, nz);
        stat_cell(e11, m1 & 8u, sl, nz);
    }
    #pragma unroll
    for (int o = 16; o; o >>= 1) {
        mx = fmaxf(mx, __shfl_xor_sync(0xFFFFFFFFu, mx, o));
        sl += __shfl_xor_sync(0xFFFFFFFFu, sl, o);
        nz += __shfl_xor_sync(0xFFFFFFFFu, nz, o);
        np += __shfl_xor_sync(0xFFFFFFFFu, np, o);
    }
    __shared__ float    smx[16], ssl[16];
    __shared__ unsigned snz[16], snp[16];
    int w = threadIdx.x >> 5;
    if ((threadIdx.x & 31) == 0) { smx[w] = mx; ssl[w] = sl; snz[w] = nz; snp[w] = np; }
    __syncthreads();   // orders: ALL CTA loads above complete before zeroing

    // Accumulator atomics FIRST (so the PDL trigger below is safe for k_sweep's
    // final-loss read), then trigger, then interior zeroing.
    if (threadIdx.x == 0) {
        float bmx = smx[0], bsl = ssl[0];
        unsigned bnz = snz[0], bnp = snp[0];
        #pragma unroll
        for (int k = 1; k < 16; k++) {
            bmx = fmaxf(bmx, smx[k]); bsl += ssl[k]; bnz += snz[k]; bnp += snp[k];
        }
        atomicMax(&g_max[s], __float_as_uint(bmx));
        atomicAdd(&g_sumlog[s], bsl);
        if (bnz) atomicAdd(&g_nzero[s], bnz);
        if (s == 0) atomicAdd(&g_npos, bnp);
    }
    __syncthreads();
    cudaTriggerProgrammaticLaunchCompletion();

    // Interior restore: zero own home uint4 in all 4 replicas. ty==0 rows
    // (row % 16 == 0) / tx==0 cols are read by neighbor CTAs -> k_sweep.
    if (ty != 0 && tx != 0) {
        const uint4 z = make_uint4(0u, 0u, 0u, 0u);
        *(uint4*)(w00 + t00) = z;
        *(uint4*)(w01 + t00) = z;
        *(uint4*)(w10 + t00) = z;
        *(uint4*)(w11 + t00) = z;
    }
}

// ---------------------------------------------------------------------------
// K3: sweep — zero the boundary tiles k_stats skipped (tile rows r % 16 == 0
// plus row 256; col pairs {0,1}+{64k,64k+1}+{256,257}), for all 224
// (scale,replica,map) planes. ~12.6 MB. Block 0 also computes the final loss
// and resets accumulators. PDL-launched; overlaps stats' zero-store tail.
// ---------------------------------------------------------------------------
#define RM   (NSC * 4 * NB)            // 224 planes
#define ROWI (17 * 129)                // row part: 17 rows x 129 uint4
#define COLI (5 * 257)                 // col part: 5 uint4-cols x 257 rows
#define SWI  (ROWI + COLI)             // 3478 uint4 per plane

__global__ void __launch_bounds__(256) k_sweep(float* __restrict__ out) {
    int gid = blockIdx.x * blockDim.x + threadIdx.x;
    int rm = 0, rest = 0, r = 0, c = 0;
    if (gid < RM * SWI) {              // index math before the dependency wait
        rm   = gid / SWI;
        rest = gid - rm * SWI;
        if (rest < ROWI) {             // full rows 0,16,...,240,256
            int rr = rest / 129;
            r = rr * 16;
            c = (rest - rr * 129) * 2;
        } else {                       // cols {0,64,128,192,256} (uint4 pairs)
            int t = rest - ROWI;
            int ci = t / 257;
            c = ci * 64;
            r = t - ci * 257;
        }
    }
    cudaGridDependencySynchronize();   // waits for stats' triggers (atomics done)
    if (gid < RM * SWI) {
        uint2* base = &g_rep[0][0][0] + (size_t)rm * MAPH;
        *(uint4*)(base + r * TTY + c) = make_uint4(0u, 0u, 0u, 0u);
    }
    if (blockIdx.x == 0 && threadIdx.x == 0) {
        float np = (float)g_npos;
        float tot = 0.f;
        #pragma unroll
        for (int i = 0; i < NSC; i++) {
            float lm = logf(__uint_as_float(g_max[i]));
            float nzf = (float)g_nzero[i];
            tot += ((np - nzf) * lm - g_sumlog[i] + 100.f * nzf) / np;
            g_sumlog[i] = 0.f; g_max[i] = 0u; g_nzero[i] = 0u;
        }
        g_npos = 0u;
        out[0] = tot;
    }
}

// ---------------------------------------------------------------------------
// Launch: scatter(+mask) -> [PDL] stats(+interior restore) -> [PDL] sweep(+final)
// ---------------------------------------------------------------------------
extern "C" void kernel_launch(void* const* d_in, const int* in_sizes, int n_in,
                              void* d_out, int out_size) {
    const float4* r3 = (const float4*)d_in[0];
    const float4* c3 = (const float4*)d_in[1];
    const float4* r4 = (const float4*)d_in[2];
    const float4* c4 = (const float4*)d_in[3];
    const float4* target = (const float4*)d_in[4];
    float* out = (float*)d_out;

    k_scatter<<<PTS / 4 / 256, 256>>>(r3, c3, r4, c4, target);  // 14336 CTAs

    cudaLaunchAttribute attr[1];
    attr[0].id = cudaLaunchAttributeProgrammaticStreamSerialization;
    attr[0].val.programmaticStreamSerializationAllowed = 1;

    cudaLaunchConfig_t cfgS = {};
    cfgS.gridDim = dim3(NSC * 512);      // 3584 CTAs x 512 threads
    cfgS.blockDim = dim3(512);
    cfgS.attrs = attr;
    cfgS.numAttrs = 1;
    cudaLaunchKernelEx(&cfgS, k_stats);

    cudaLaunchConfig_t cfgW = {};
    cfgW.gridDim = dim3((RM * SWI + 255) / 256);   // 3043 CTAs
    cfgW.blockDim = dim3(256);
    cfgW.attrs = attr;
    cfgW.numAttrs = 1;
    cudaLaunchKernelEx(&cfgW, k_sweep, out);
}